// round 5
// baseline (speedup 1.0000x reference)
#include <cuda_runtime.h>
#include <cstdint>

#define HDIM 128
#define NMAX 100032          // 782 * 128
#define GMAX 1024
#define NCLS 10
#define BN_EPS 1e-5
#define SLOPE 0.01f

// ---------------- device scratch (static, no allocation) ----------------
__device__ __align__(16) float  g_agg[(size_t)NMAX * HDIM];   // neighbor aggregation
__device__ __align__(16) float  g_t  [(size_t)NMAX * HDIM];   // intermediate
__device__ __align__(16) float  g_h  [(size_t)NMAX * HDIM];   // layer-1 output (pre-BN)
__device__ __align__(16) float  g_hg [GMAX * HDIM];           // pooled RAW graph sums
__device__ __align__(16) float  g_cnt[GMAX];                  // nodes per graph
__device__ __align__(16) double g_stats[2 * HDIM];            // col sums / sumsq
__device__ __align__(16) float  g_coef [2 * HDIM];            // BN affine: a, c

__device__ __forceinline__ float lrelu(float x) { return x > 0.f ? x : SLOPE * x; }

// ---------------- zero scratch ----------------
template<int FIRST>
__global__ void zero_kernel(int nf) {
    int idx    = blockIdx.x * blockDim.x + threadIdx.x;
    int stride = gridDim.x * blockDim.x;
    float4 z = make_float4(0.f, 0.f, 0.f, 0.f);
    float4* a4 = reinterpret_cast<float4*>(g_agg);
    int n4 = nf >> 2;
    for (int i = idx; i < n4; i += stride) a4[i] = z;
    if (FIRST) {
        float4* h4 = reinterpret_cast<float4*>(g_hg);
        for (int i = idx; i < (GMAX * HDIM) >> 2; i += stride) h4[i] = z;
        if (idx < GMAX) g_cnt[idx] = 0.f;
    }
    if (idx < 2 * HDIM) g_stats[idx] = 0.0;
}

// ---------------- node counts per graph ----------------
__global__ void count_kernel(const int* __restrict__ batch, int N) {
    int i = blockIdx.x * blockDim.x + threadIdx.x;
    if (i < N) atomicAdd(&g_cnt[batch[i]], 1.0f);
}

// ---------------- edge scatter: agg[dst] += (BN?)X[src], one warp per edge ----------------
template<int APPLY_BN>
__global__ void scatter_kernel(const float* __restrict__ Xext,
                               const int* __restrict__ src,
                               const int* __restrict__ dst,
                               int E) {
    int w = (blockIdx.x * blockDim.x + threadIdx.x) >> 5;
    if (w >= E) return;
    int lane = threadIdx.x & 31;
    const float* X = APPLY_BN ? g_h : Xext;
    int s = src[w];
    int d = dst[w];
    float4 v = *reinterpret_cast<const float4*>(X + (size_t)s * HDIM + lane * 4);
    if (APPLY_BN) {
        float4 a = *reinterpret_cast<const float4*>(&g_coef[lane * 4]);
        float4 c = *reinterpret_cast<const float4*>(&g_coef[HDIM + lane * 4]);
        v.x = fmaf(a.x, v.x, c.x);
        v.y = fmaf(a.y, v.y, c.y);
        v.z = fmaf(a.z, v.z, c.z);
        v.w = fmaf(a.w, v.w, c.w);
    }
    float* p = g_agg + (size_t)d * HDIM + lane * 4;
    asm volatile("red.global.add.v4.f32 [%0], {%1, %2, %3, %4};"
                 :: "l"(p), "f"(v.x), "f"(v.y), "f"(v.z), "f"(v.w)
                 : "memory");
}

// ---------------- fused GEMM: [N,128] @ [128,128] + bias, leaky ----------------
// MODE 0: A = (BN?)X + g_agg, out = g_t
// MODE 1: A = g_t, out = g_h (unless POOL) + BN stats; POOL: raw per-graph sums
// Block: 256 threads, 128 rows x 128 cols, BK=16, per-thread 8x8.
template<int MODE, int APPLY_BN, int POOL>
__global__ void __launch_bounds__(256, 2)
gemm_kernel(const float* __restrict__ Xext,
            const float* __restrict__ W,
            const float* __restrict__ bias,
            const int* __restrict__ batch,
            int N) {
    __shared__ __align__(16) float As[16][132];   // [k][row], pad=132 (16B-aligned rows, 2-way STS max)
    __shared__ __align__(16) float Ws[16][HDIM];  // [k][col]
    __shared__ float csum[HDIM];
    __shared__ float csq [HDIM];

    const int tid  = threadIdx.x;
    const int tcol = tid & 15;         // cols tcol*8 .. +7
    const int trow = tid >> 4;         // rows trow*8 .. +7 (contiguous!)
    const int row0 = blockIdx.x * 128;

    const float* X;
    if (MODE == 0) X = APPLY_BN ? g_h : Xext;
    else           X = g_t;

    float acc[8][8];
#pragma unroll
    for (int i = 0; i < 8; i++)
#pragma unroll
        for (int j = 0; j < 8; j++) acc[i][j] = 0.f;

    for (int k0 = 0; k0 < HDIM; k0 += 16) {
        // ---- A tile (transposed into smem) ----
#pragma unroll
        for (int it = 0; it < 2; it++) {
            int idx = tid + it * 256;
            int r   = idx >> 2;            // 0..127
            int kq  = (idx & 3) * 4;       // 0,4,8,12
            float4 av = make_float4(0.f, 0.f, 0.f, 0.f);
            int grow = row0 + r;
            if (grow < N) {
                av = *reinterpret_cast<const float4*>(X + (size_t)grow * HDIM + k0 + kq);
                if (APPLY_BN) {
                    float4 a = *reinterpret_cast<const float4*>(&g_coef[k0 + kq]);
                    float4 c = *reinterpret_cast<const float4*>(&g_coef[HDIM + k0 + kq]);
                    av.x = fmaf(a.x, av.x, c.x);
                    av.y = fmaf(a.y, av.y, c.y);
                    av.z = fmaf(a.z, av.z, c.z);
                    av.w = fmaf(a.w, av.w, c.w);
                }
                if (MODE == 0) {
                    float4 gv = *reinterpret_cast<const float4*>(g_agg + (size_t)grow * HDIM + k0 + kq);
                    av.x += gv.x; av.y += gv.y; av.z += gv.z; av.w += gv.w;
                }
            }
            As[kq + 0][r] = av.x;
            As[kq + 1][r] = av.y;
            As[kq + 2][r] = av.z;
            As[kq + 3][r] = av.w;
        }
        // ---- W tile ----
        {
            const float4* wsrc = reinterpret_cast<const float4*>(W + k0 * HDIM);
            float4* wdst = reinterpret_cast<float4*>(&Ws[0][0]);
            wdst[tid]       = wsrc[tid];
            wdst[tid + 256] = wsrc[tid + 256];
        }
        __syncthreads();

#pragma unroll
        for (int kk = 0; kk < 16; kk++) {
            float4 w0 = *reinterpret_cast<const float4*>(&Ws[kk][tcol * 8]);
            float4 w1 = *reinterpret_cast<const float4*>(&Ws[kk][tcol * 8 + 4]);
            float4 a0 = *reinterpret_cast<const float4*>(&As[kk][trow * 8]);
            float4 a1 = *reinterpret_cast<const float4*>(&As[kk][trow * 8 + 4]);
            float a[8] = {a0.x, a0.y, a0.z, a0.w, a1.x, a1.y, a1.z, a1.w};
            float w[8] = {w0.x, w0.y, w0.z, w0.w, w1.x, w1.y, w1.z, w1.w};
#pragma unroll
            for (int i = 0; i < 8; i++)
#pragma unroll
                for (int j = 0; j < 8; j++)
                    acc[i][j] = fmaf(a[i], w[j], acc[i][j]);
        }
        __syncthreads();
    }

    float4 b0 = *reinterpret_cast<const float4*>(bias + tcol * 8);
    float4 b1 = *reinterpret_cast<const float4*>(bias + tcol * 8 + 4);
    float bv[8] = {b0.x, b0.y, b0.z, b0.w, b1.x, b1.y, b1.z, b1.w};

    if (MODE == 0) {
#pragma unroll
        for (int i = 0; i < 8; i++) {
            int grow = row0 + trow * 8 + i;
            if (grow < N) {
                float o[8];
#pragma unroll
                for (int j = 0; j < 8; j++) o[j] = lrelu(acc[i][j] + bv[j]);
                float* dst = g_t + (size_t)grow * HDIM + tcol * 8;
                *reinterpret_cast<float4*>(dst)     = make_float4(o[0], o[1], o[2], o[3]);
                *reinterpret_cast<float4*>(dst + 4) = make_float4(o[4], o[5], o[6], o[7]);
            }
        }
    } else {
        float s0[8], s1[8];
#pragma unroll
        for (int j = 0; j < 8; j++) { s0[j] = 0.f; s1[j] = 0.f; }

        // pooling run-accumulators (batch is sorted -> few runs per 8 rows)
        int curg = -1;
        float p[8];
#pragma unroll
        for (int j = 0; j < 8; j++) p[j] = 0.f;

#pragma unroll
        for (int i = 0; i < 8; i++) {
            int grow = row0 + trow * 8 + i;
            if (grow < N) {
                float o[8];
#pragma unroll
                for (int j = 0; j < 8; j++) {
                    o[j] = lrelu(acc[i][j] + bv[j]);
                    s0[j] += o[j];
                    s1[j] += o[j] * o[j];
                }
                if (!POOL) {
                    float* dst = g_h + (size_t)grow * HDIM + tcol * 8;
                    *reinterpret_cast<float4*>(dst)     = make_float4(o[0], o[1], o[2], o[3]);
                    *reinterpret_cast<float4*>(dst + 4) = make_float4(o[4], o[5], o[6], o[7]);
                } else {
                    int g = batch[grow];
                    if (g != curg) {
                        if (curg >= 0) {
                            float* dst = g_hg + (size_t)curg * HDIM + tcol * 8;
                            asm volatile("red.global.add.v4.f32 [%0], {%1, %2, %3, %4};"
                                         :: "l"(dst), "f"(p[0]), "f"(p[1]), "f"(p[2]), "f"(p[3]) : "memory");
                            asm volatile("red.global.add.v4.f32 [%0], {%1, %2, %3, %4};"
                                         :: "l"(dst + 4), "f"(p[4]), "f"(p[5]), "f"(p[6]), "f"(p[7]) : "memory");
                        }
                        curg = g;
#pragma unroll
                        for (int j = 0; j < 8; j++) p[j] = 0.f;
                    }
#pragma unroll
                    for (int j = 0; j < 8; j++) p[j] += o[j];
                }
            }
        }
        if (POOL && curg >= 0) {
            float* dst = g_hg + (size_t)curg * HDIM + tcol * 8;
            asm volatile("red.global.add.v4.f32 [%0], {%1, %2, %3, %4};"
                         :: "l"(dst), "f"(p[0]), "f"(p[1]), "f"(p[2]), "f"(p[3]) : "memory");
            asm volatile("red.global.add.v4.f32 [%0], {%1, %2, %3, %4};"
                         :: "l"(dst + 4), "f"(p[4]), "f"(p[5]), "f"(p[6]), "f"(p[7]) : "memory");
        }

        // BN statistics reduction
        if (tid < HDIM) { csum[tid] = 0.f; csq[tid] = 0.f; }
        __syncthreads();
#pragma unroll
        for (int j = 0; j < 8; j++) {
            atomicAdd(&csum[tcol * 8 + j], s0[j]);
            atomicAdd(&csq [tcol * 8 + j], s1[j]);
        }
        __syncthreads();
        if (tid < HDIM) {
            atomicAdd(&g_stats[tid],        (double)csum[tid]);
            atomicAdd(&g_stats[HDIM + tid], (double)csq[tid]);
        }
    }
}

// ---------------- BN coefficients: a = g/sqrt(var+eps), c = be - a*mean ----------------
__global__ void coef_kernel(const float* __restrict__ gamma,
                            const float* __restrict__ beta, int N) {
    int c = threadIdx.x;
    double mean = g_stats[c] / (double)N;
    double var  = g_stats[HDIM + c] / (double)N - mean * mean;
    float a = (float)((double)gamma[c] / sqrt(var + (double)BN_EPS));
    g_coef[c]        = a;
    g_coef[HDIM + c] = beta[c] - a * (float)mean;
}

// ---------------- head: hg = a2*raw + c2*cnt, MLP + log_softmax ----------------
__global__ void head_kernel(const float* __restrict__ fcW1, const float* __restrict__ fcb1,
                            const float* __restrict__ fcW2, const float* __restrict__ fcb2,
                            float* __restrict__ out) {
    __shared__ float s[HDIM];
    __shared__ float y[HDIM];
    __shared__ float z[NCLS];
    __shared__ float red2[2];
    int g = blockIdx.x;
    int j = threadIdx.x;

    float cnt = g_cnt[g];
    s[j] = g_coef[j] * g_hg[g * HDIM + j] + g_coef[HDIM + j] * cnt;
    __syncthreads();

    float acc = fcb1[j];
#pragma unroll 8
    for (int k = 0; k < HDIM; k++) acc += s[k] * fcW1[k * HDIM + j];
    y[j] = lrelu(acc);
    __syncthreads();

    if (j < NCLS) {
        float acc2 = fcb2[j];
#pragma unroll 8
        for (int k = 0; k < HDIM; k++) acc2 += y[k] * fcW2[k * NCLS + j];
        z[j] = acc2;
    }
    __syncthreads();

    if (j == 0) {
        float m = z[0];
#pragma unroll
        for (int c = 1; c < NCLS; c++) m = fmaxf(m, z[c]);
        float se = 0.f;
#pragma unroll
        for (int c = 0; c < NCLS; c++) se += expf(z[c] - m);
        red2[0] = m;
        red2[1] = logf(se);
    }
    __syncthreads();
    if (j < NCLS) out[g * NCLS + j] = z[j] - red2[0] - red2[1];
}

// ---------------- launch ----------------
extern "C" void kernel_launch(void* const* d_in, const int* in_sizes, int n_in,
                              void* d_out, int out_size) {
    const float* x    = (const float*)d_in[0];
    const float* W1a  = (const float*)d_in[1];
    const float* b1a  = (const float*)d_in[2];
    const float* W1b  = (const float*)d_in[3];
    const float* b1b  = (const float*)d_in[4];
    const float* g1   = (const float*)d_in[5];
    const float* be1  = (const float*)d_in[6];
    const float* W2a  = (const float*)d_in[7];
    const float* b2a  = (const float*)d_in[8];
    const float* W2b  = (const float*)d_in[9];
    const float* b2b  = (const float*)d_in[10];
    const float* g2   = (const float*)d_in[11];
    const float* be2  = (const float*)d_in[12];
    const float* fcW1 = (const float*)d_in[13];
    const float* fcb1 = (const float*)d_in[14];
    const float* fcW2 = (const float*)d_in[15];
    const float* fcb2 = (const float*)d_in[16];
    const int* ei     = (const int*)d_in[17];   // int32 (JAX x64 disabled)
    const int* batch  = (const int*)d_in[18];   // int32
    float* out = (float*)d_out;

    const int N = in_sizes[0] / HDIM;
    const int E = in_sizes[17] / 2;

    const int gemmBlocks = (N + 127) / 128;
    const int scatBlocks = (E + 7) / 8;     // 8 warps per block

    // ---- layer 1 ----
    zero_kernel<1><<<1024, 256>>>(N * HDIM);
    count_kernel<<<(N + 255) / 256, 256>>>(batch, N);
    scatter_kernel<0><<<scatBlocks, 256>>>(x, ei, ei + E, E);
    gemm_kernel<0, 0, 0><<<gemmBlocks, 256>>>(x, W1a, b1a, nullptr, N);
    gemm_kernel<1, 0, 0><<<gemmBlocks, 256>>>(nullptr, W1b, b1b, nullptr, N);
    coef_kernel<<<1, HDIM>>>(g1, be1, N);

    // ---- layer 2 (BN1 folded into reads) ----
    zero_kernel<0><<<1024, 256>>>(N * HDIM);
    scatter_kernel<1><<<scatBlocks, 256>>>(nullptr, ei, ei + E, E);
    gemm_kernel<0, 1, 0><<<gemmBlocks, 256>>>(nullptr, W2a, b2a, nullptr, N);
    gemm_kernel<1, 0, 1><<<gemmBlocks, 256>>>(nullptr, W2b, b2b, batch, N);
    coef_kernel<<<1, HDIM>>>(g2, be2, N);

    // ---- head (applies BN2 affine via raw sums + counts) ----
    head_kernel<<<GMAX, HDIM>>>(fcW1, fcb1, fcW2, fcb2, out);
}

// round 6
// speedup vs baseline: 1.3104x; 1.3104x over previous
#include <cuda_runtime.h>
#include <cstdint>

#define HDIM 128
#define NMAX 100032
#define EMAX 1600000
#define GMAX 1024
#define NCLS 10
#define BN_EPS 1e-5
#define SLOPE 0.01f

// ---------------- device scratch (static, no allocation) ----------------
__device__ __align__(16) float  g_agg[(size_t)NMAX * HDIM];   // A matrix for GEMM-a (x+agg, BN applied)
__device__ __align__(16) float  g_t  [(size_t)NMAX * HDIM];   // intermediate
__device__ __align__(16) float  g_h  [(size_t)NMAX * HDIM];   // layer-1 output (pre-BN)
__device__ __align__(16) float  g_hg [GMAX * HDIM];           // pooled RAW graph sums
__device__ __align__(16) float  g_cnt[GMAX];                  // nodes per graph
__device__ __align__(16) double g_stats[2 * HDIM];            // col sums / sumsq
__device__ __align__(16) float  g_coef [2 * HDIM];            // BN affine: a, c
__device__ int g_deg   [NMAX];
__device__ int g_rowptr[NMAX + 1];
__device__ int g_cur   [NMAX];
__device__ int g_eidx  [EMAX];

__device__ __forceinline__ float lrelu(float x) { return x > 0.f ? x : SLOPE * x; }

// ---------------- zero small scratch + CSR counters ----------------
__global__ void zero_kernel(int N) {
    int idx    = blockIdx.x * blockDim.x + threadIdx.x;
    int stride = gridDim.x * blockDim.x;
    float4 z = make_float4(0.f, 0.f, 0.f, 0.f);
    float4* h4 = reinterpret_cast<float4*>(g_hg);
    for (int i = idx; i < (GMAX * HDIM) >> 2; i += stride) h4[i] = z;
    for (int i = idx; i < N; i += stride) { g_deg[i] = 0; g_cur[i] = 0; }
    if (idx < GMAX) g_cnt[idx] = 0.f;
    if (idx < 2 * HDIM) g_stats[idx] = 0.0;
}

// zero only BN stats (before layer 2)
__global__ void zstats_kernel() {
    int idx = threadIdx.x;
    if (idx < 2 * HDIM) g_stats[idx] = 0.0;
}

// ---------------- node counts per graph ----------------
__global__ void count_kernel(const int* __restrict__ batch, int N) {
    int i = blockIdx.x * blockDim.x + threadIdx.x;
    if (i < N) atomicAdd(&g_cnt[batch[i]], 1.0f);
}

// ---------------- CSR build: histogram ----------------
__global__ void hist_kernel(const int* __restrict__ dst, int E) {
    int e = blockIdx.x * blockDim.x + threadIdx.x;
    if (e < E) atomicAdd(&g_deg[dst[e]], 1);
}

// ---------------- CSR build: single-block exclusive scan ----------------
__global__ void scan_kernel(int N) {
    __shared__ int ts[1024];
    int t = threadIdx.x;
    int chunk = (N + 1023) >> 10;
    int lo = t * chunk;
    int hi = min(lo + chunk, N);
    if (lo > N) lo = N;
    int s = 0;
    for (int i = lo; i < hi; i++) s += g_deg[i];
    ts[t] = s;
    __syncthreads();
    // Hillis-Steele inclusive scan
    for (int off = 1; off < 1024; off <<= 1) {
        int v = (t >= off) ? ts[t - off] : 0;
        __syncthreads();
        ts[t] += v;
        __syncthreads();
    }
    int run = ts[t] - s;   // exclusive prefix for this chunk
    for (int i = lo; i < hi; i++) { g_rowptr[i] = run; run += g_deg[i]; }
    if (t == 1023) g_rowptr[N] = run;
}

// ---------------- CSR build: fill edge lists ----------------
__global__ void fill_kernel(const int* __restrict__ src,
                            const int* __restrict__ dst, int E) {
    int e = blockIdx.x * blockDim.x + threadIdx.x;
    if (e < E) {
        int d = dst[e];
        int pos = atomicAdd(&g_cur[d], 1);
        g_eidx[g_rowptr[d] + pos] = src[e];
    }
}

// ---------------- gather aggregation: agg[i] = BN?( x[i] + sum_{j->i} x[j] ) ----------------
// one warp per node; APPLY_BN folds BN1 affine: a*(raw sum) + (deg+1)*c
template<int APPLY_BN>
__global__ void aggregate_kernel(const float* __restrict__ Xext, int N) {
    int i = (blockIdx.x * blockDim.x + threadIdx.x) >> 5;
    if (i >= N) return;
    int lane = threadIdx.x & 31;
    const float* X = APPLY_BN ? g_h : Xext;
    int base = g_rowptr[i];
    int end  = g_rowptr[i + 1];

    float4 acc = *reinterpret_cast<const float4*>(X + (size_t)i * HDIM + lane * 4);
    int e = base;
    for (; e + 4 <= end; e += 4) {
        int s0 = g_eidx[e], s1 = g_eidx[e + 1], s2 = g_eidx[e + 2], s3 = g_eidx[e + 3];
        float4 v0 = *reinterpret_cast<const float4*>(X + (size_t)s0 * HDIM + lane * 4);
        float4 v1 = *reinterpret_cast<const float4*>(X + (size_t)s1 * HDIM + lane * 4);
        float4 v2 = *reinterpret_cast<const float4*>(X + (size_t)s2 * HDIM + lane * 4);
        float4 v3 = *reinterpret_cast<const float4*>(X + (size_t)s3 * HDIM + lane * 4);
        acc.x += v0.x + v1.x + v2.x + v3.x;
        acc.y += v0.y + v1.y + v2.y + v3.y;
        acc.z += v0.z + v1.z + v2.z + v3.z;
        acc.w += v0.w + v1.w + v2.w + v3.w;
    }
    for (; e < end; e++) {
        int s = g_eidx[e];
        float4 v = *reinterpret_cast<const float4*>(X + (size_t)s * HDIM + lane * 4);
        acc.x += v.x; acc.y += v.y; acc.z += v.z; acc.w += v.w;
    }
    if (APPLY_BN) {
        float cnt = (float)(end - base + 1);
        float4 a = *reinterpret_cast<const float4*>(&g_coef[lane * 4]);
        float4 c = *reinterpret_cast<const float4*>(&g_coef[HDIM + lane * 4]);
        acc.x = fmaf(a.x, acc.x, cnt * c.x);
        acc.y = fmaf(a.y, acc.y, cnt * c.y);
        acc.z = fmaf(a.z, acc.z, cnt * c.z);
        acc.w = fmaf(a.w, acc.w, cnt * c.w);
    }
    *reinterpret_cast<float4*>(g_agg + (size_t)i * HDIM + lane * 4) = acc;
}

// ---------------- fused GEMM (R3 tiling): [N,128] @ [128,128] + bias, leaky ----------------
// MODE 0: A = g_agg, out = g_t
// MODE 1: A = g_t, out = g_h (or pooled raw sums if POOL) + BN stats
// Block: 256 threads, 64 rows x 128 cols, BK=16. warp = 8 rows, lane = 4 cols.
template<int MODE, int POOL>
__global__ void __launch_bounds__(256)
gemm_kernel(const float* __restrict__ W,
            const float* __restrict__ bias,
            const int* __restrict__ batch,
            int N) {
    __shared__ __align__(16) float As[16][72];
    __shared__ __align__(16) float Ws[16 * HDIM];
    __shared__ float csum[HDIM];
    __shared__ float csq [HDIM];

    const int tid  = threadIdx.x;
    const int tcol = tid & 31;
    const int trow = tid >> 5;
    const int row0 = blockIdx.x * 64;

    const float* X = (MODE == 0) ? g_agg : g_t;

    float acc[8][4];
#pragma unroll
    for (int i = 0; i < 8; i++)
#pragma unroll
        for (int j = 0; j < 4; j++) acc[i][j] = 0.f;

    const int lr = tid >> 2;
    const int lk = (tid & 3) * 4;

    for (int k0 = 0; k0 < HDIM; k0 += 16) {
        float4 av = make_float4(0.f, 0.f, 0.f, 0.f);
        int grow = row0 + lr;
        if (grow < N)
            av = *reinterpret_cast<const float4*>(X + (size_t)grow * HDIM + k0 + lk);
        As[lk + 0][lr] = av.x;
        As[lk + 1][lr] = av.y;
        As[lk + 2][lr] = av.z;
        As[lk + 3][lr] = av.w;

        const float4* wsrc = reinterpret_cast<const float4*>(W + k0 * HDIM);
        float4* wdst = reinterpret_cast<float4*>(Ws);
        wdst[tid]       = wsrc[tid];
        wdst[tid + 256] = wsrc[tid + 256];
        __syncthreads();

#pragma unroll
        for (int kk = 0; kk < 16; kk++) {
            float4 w  = *reinterpret_cast<float4*>(&Ws[kk * HDIM + tcol * 4]);
            float4 a0 = *reinterpret_cast<float4*>(&As[kk][trow * 8]);
            float4 a1 = *reinterpret_cast<float4*>(&As[kk][trow * 8 + 4]);
            float a[8] = {a0.x, a0.y, a0.z, a0.w, a1.x, a1.y, a1.z, a1.w};
#pragma unroll
            for (int i = 0; i < 8; i++) {
                acc[i][0] = fmaf(a[i], w.x, acc[i][0]);
                acc[i][1] = fmaf(a[i], w.y, acc[i][1]);
                acc[i][2] = fmaf(a[i], w.z, acc[i][2]);
                acc[i][3] = fmaf(a[i], w.w, acc[i][3]);
            }
        }
        __syncthreads();
    }

    float4 bv = *reinterpret_cast<const float4*>(bias + tcol * 4);

    if (MODE == 0) {
#pragma unroll
        for (int i = 0; i < 8; i++) {
            int grow = row0 + trow * 8 + i;
            if (grow < N) {
                float4 o;
                o.x = lrelu(acc[i][0] + bv.x);
                o.y = lrelu(acc[i][1] + bv.y);
                o.z = lrelu(acc[i][2] + bv.z);
                o.w = lrelu(acc[i][3] + bv.w);
                *reinterpret_cast<float4*>(g_t + (size_t)grow * HDIM + tcol * 4) = o;
            }
        }
    } else {
        float s0[4] = {0.f, 0.f, 0.f, 0.f};
        float s1[4] = {0.f, 0.f, 0.f, 0.f};
        int curg = -1;
        float p[4] = {0.f, 0.f, 0.f, 0.f};

#pragma unroll
        for (int i = 0; i < 8; i++) {
            int grow = row0 + trow * 8 + i;
            if (grow < N) {
                float4 o;
                o.x = lrelu(acc[i][0] + bv.x);
                o.y = lrelu(acc[i][1] + bv.y);
                o.z = lrelu(acc[i][2] + bv.z);
                o.w = lrelu(acc[i][3] + bv.w);
                s0[0] += o.x; s1[0] += o.x * o.x;
                s0[1] += o.y; s1[1] += o.y * o.y;
                s0[2] += o.z; s1[2] += o.z * o.z;
                s0[3] += o.w; s1[3] += o.w * o.w;
                if (!POOL) {
                    *reinterpret_cast<float4*>(g_h + (size_t)grow * HDIM + tcol * 4) = o;
                } else {
                    int g = batch[grow];
                    if (g != curg) {
                        if (curg >= 0) {
                            float* dstp = g_hg + (size_t)curg * HDIM + tcol * 4;
                            asm volatile("red.global.add.v4.f32 [%0], {%1, %2, %3, %4};"
                                         :: "l"(dstp), "f"(p[0]), "f"(p[1]), "f"(p[2]), "f"(p[3]) : "memory");
                        }
                        curg = g;
                        p[0] = p[1] = p[2] = p[3] = 0.f;
                    }
                    p[0] += o.x; p[1] += o.y; p[2] += o.z; p[3] += o.w;
                }
            }
        }
        if (POOL && curg >= 0) {
            float* dstp = g_hg + (size_t)curg * HDIM + tcol * 4;
            asm volatile("red.global.add.v4.f32 [%0], {%1, %2, %3, %4};"
                         :: "l"(dstp), "f"(p[0]), "f"(p[1]), "f"(p[2]), "f"(p[3]) : "memory");
        }

        if (tid < HDIM) { csum[tid] = 0.f; csq[tid] = 0.f; }
        __syncthreads();
#pragma unroll
        for (int j = 0; j < 4; j++) {
            atomicAdd(&csum[tcol * 4 + j], s0[j]);
            atomicAdd(&csq [tcol * 4 + j], s1[j]);
        }
        __syncthreads();
        if (tid < HDIM) {
            atomicAdd(&g_stats[tid],        (double)csum[tid]);
            atomicAdd(&g_stats[HDIM + tid], (double)csq[tid]);
        }
    }
}

// ---------------- BN coefficients: a = g/sqrt(var+eps), c = be - a*mean ----------------
__global__ void coef_kernel(const float* __restrict__ gamma,
                            const float* __restrict__ beta, int N) {
    int c = threadIdx.x;
    double mean = g_stats[c] / (double)N;
    double var  = g_stats[HDIM + c] / (double)N - mean * mean;
    float a = (float)((double)gamma[c] / sqrt(var + (double)BN_EPS));
    g_coef[c]        = a;
    g_coef[HDIM + c] = beta[c] - a * (float)mean;
}

// ---------------- head: hg = a2*raw + c2*cnt, MLP + log_softmax ----------------
__global__ void head_kernel(const float* __restrict__ fcW1, const float* __restrict__ fcb1,
                            const float* __restrict__ fcW2, const float* __restrict__ fcb2,
                            float* __restrict__ out) {
    __shared__ float s[HDIM];
    __shared__ float y[HDIM];
    __shared__ float z[NCLS];
    __shared__ float red2[2];
    int g = blockIdx.x;
    int j = threadIdx.x;

    float cnt = g_cnt[g];
    s[j] = g_coef[j] * g_hg[g * HDIM + j] + g_coef[HDIM + j] * cnt;
    __syncthreads();

    float acc = fcb1[j];
#pragma unroll 8
    for (int k = 0; k < HDIM; k++) acc += s[k] * fcW1[k * HDIM + j];
    y[j] = lrelu(acc);
    __syncthreads();

    if (j < NCLS) {
        float acc2 = fcb2[j];
#pragma unroll 8
        for (int k = 0; k < HDIM; k++) acc2 += y[k] * fcW2[k * NCLS + j];
        z[j] = acc2;
    }
    __syncthreads();

    if (j == 0) {
        float m = z[0];
#pragma unroll
        for (int c = 1; c < NCLS; c++) m = fmaxf(m, z[c]);
        float se = 0.f;
#pragma unroll
        for (int c = 0; c < NCLS; c++) se += expf(z[c] - m);
        red2[0] = m;
        red2[1] = logf(se);
    }
    __syncthreads();
    if (j < NCLS) out[g * NCLS + j] = z[j] - red2[0] - red2[1];
}

// ---------------- launch ----------------
extern "C" void kernel_launch(void* const* d_in, const int* in_sizes, int n_in,
                              void* d_out, int out_size) {
    const float* x    = (const float*)d_in[0];
    const float* W1a  = (const float*)d_in[1];
    const float* b1a  = (const float*)d_in[2];
    const float* W1b  = (const float*)d_in[3];
    const float* b1b  = (const float*)d_in[4];
    const float* g1   = (const float*)d_in[5];
    const float* be1  = (const float*)d_in[6];
    const float* W2a  = (const float*)d_in[7];
    const float* b2a  = (const float*)d_in[8];
    const float* W2b  = (const float*)d_in[9];
    const float* b2b  = (const float*)d_in[10];
    const float* g2   = (const float*)d_in[11];
    const float* be2  = (const float*)d_in[12];
    const float* fcW1 = (const float*)d_in[13];
    const float* fcb1 = (const float*)d_in[14];
    const float* fcW2 = (const float*)d_in[15];
    const float* fcb2 = (const float*)d_in[16];
    const int* ei     = (const int*)d_in[17];   // int32 (JAX x64 disabled)
    const int* batch  = (const int*)d_in[18];   // int32
    float* out = (float*)d_out;

    const int N = in_sizes[0] / HDIM;
    const int E = in_sizes[17] / 2;
    const int* esrc = ei;
    const int* edst = ei + E;

    const int gemmBlocks = (N + 63) / 64;
    const int aggBlocks  = (N + 7) / 8;      // warp per node, 8 warps/block
    const int eBlocks    = (E + 255) / 256;

    // ---- CSR build (once, reused by both layers) ----
    zero_kernel<<<512, 256>>>(N);
    count_kernel<<<(N + 255) / 256, 256>>>(batch, N);
    hist_kernel<<<eBlocks, 256>>>(edst, E);
    scan_kernel<<<1, 1024>>>(N);
    fill_kernel<<<eBlocks, 256>>>(esrc, edst, E);

    // ---- layer 1 ----
    aggregate_kernel<0><<<aggBlocks, 256>>>(x, N);
    gemm_kernel<0, 0><<<gemmBlocks, 256>>>(W1a, b1a, nullptr, N);
    gemm_kernel<1, 0><<<gemmBlocks, 256>>>(W1b, b1b, nullptr, N);
    coef_kernel<<<1, HDIM>>>(g1, be1, N);

    // ---- layer 2 (BN1 folded into aggregation) ----
    zstats_kernel<<<1, 256>>>();
    aggregate_kernel<1><<<aggBlocks, 256>>>(nullptr, N);
    gemm_kernel<0, 0><<<gemmBlocks, 256>>>(W2a, b2a, nullptr, N);
    gemm_kernel<1, 1><<<gemmBlocks, 256>>>(W2b, b2b, batch, N);
    coef_kernel<<<1, HDIM>>>(g2, be2, N);

    // ---- head (applies BN2 affine via raw sums + counts) ----
    head_kernel<<<GMAX, HDIM>>>(fcW1, fcb1, fcW2, fcb2, out);
}

// round 7
// speedup vs baseline: 1.6054x; 1.2251x over previous
#include <cuda_runtime.h>
#include <cstdint>

#define HDIM 128
#define NMAX 100032
#define EMAX 1600000
#define GMAX 1024
#define NCLS 10
#define BN_EPS 1e-5
#define SLOPE 0.01f
#define SCAN_CHUNK 2048
#define MAXBLK 64            // >= ceil(NMAX / SCAN_CHUNK) = 49

// ---------------- device scratch (static, no allocation) ----------------
__device__ __align__(16) float  g_agg[(size_t)NMAX * HDIM];
__device__ __align__(16) float  g_t  [(size_t)NMAX * HDIM];
__device__ __align__(16) float  g_h  [(size_t)NMAX * HDIM];
__device__ __align__(16) float  g_hg [GMAX * HDIM];
__device__ __align__(16) float  g_cnt[GMAX];
__device__ __align__(16) double g_stats[2 * HDIM];
__device__ __align__(16) float  g_coef [2 * HDIM];
__device__ int g_deg   [NMAX];
__device__ int g_rowptr[NMAX + 1];
__device__ int g_cur   [NMAX];
__device__ int g_eidx  [EMAX];
__device__ int g_bsum  [MAXBLK];
__device__ int g_boff  [MAXBLK];

__device__ __forceinline__ float lrelu(float x) { return x > 0.f ? x : SLOPE * x; }

// ---------------- zero small scratch + CSR counters ----------------
__global__ void zero_kernel(int N) {
    int idx    = blockIdx.x * blockDim.x + threadIdx.x;
    int stride = gridDim.x * blockDim.x;
    float4 z = make_float4(0.f, 0.f, 0.f, 0.f);
    float4* h4 = reinterpret_cast<float4*>(g_hg);
    for (int i = idx; i < (GMAX * HDIM) >> 2; i += stride) h4[i] = z;
    for (int i = idx; i < N; i += stride) { g_deg[i] = 0; g_cur[i] = 0; }
    if (idx < GMAX) g_cnt[idx] = 0.f;
    if (idx < 2 * HDIM) g_stats[idx] = 0.0;
}

__global__ void zstats_kernel() {
    int idx = threadIdx.x;
    if (idx < 2 * HDIM) g_stats[idx] = 0.0;
}

// ---------------- node counts per graph ----------------
__global__ void count_kernel(const int* __restrict__ batch, int N) {
    int i = blockIdx.x * blockDim.x + threadIdx.x;
    if (i < N) atomicAdd(&g_cnt[batch[i]], 1.0f);
}

// ---------------- CSR build: histogram ----------------
__global__ void hist_kernel(const int* __restrict__ dst, int E) {
    int e = blockIdx.x * blockDim.x + threadIdx.x;
    if (e < E) atomicAdd(&g_deg[dst[e]], 1);
}

// ---------------- CSR build: 3-phase multi-block exclusive scan ----------------
// phase 1: per-block exclusive scans over 2048-element chunks + block totals
__global__ void scan1_kernel(int N) {
    __shared__ int ts[256];
    int b = blockIdx.x;
    int t = threadIdx.x;
    int base = b * SCAN_CHUNK + t * 8;
    int v[8];
    int s = 0;
#pragma unroll
    for (int i = 0; i < 8; i++) {
        int idx = base + i;
        v[i] = (idx < N) ? g_deg[idx] : 0;
        s += v[i];
    }
    ts[t] = s;
    __syncthreads();
#pragma unroll
    for (int off = 1; off < 256; off <<= 1) {
        int x = (t >= off) ? ts[t - off] : 0;
        __syncthreads();
        ts[t] += x;
        __syncthreads();
    }
    int run = ts[t] - s;   // exclusive prefix within block
#pragma unroll
    for (int i = 0; i < 8; i++) {
        int idx = base + i;
        if (idx < N) g_rowptr[idx] = run;
        run += v[i];
    }
    if (t == 255) g_bsum[b] = ts[255];
}

// phase 2: scan the block totals (single tiny block)
__global__ void scan2_kernel(int nb) {
    __shared__ int ts[MAXBLK];
    int t = threadIdx.x;
    int v = (t < nb) ? g_bsum[t] : 0;
    ts[t] = v;
    __syncthreads();
#pragma unroll
    for (int off = 1; off < MAXBLK; off <<= 1) {
        int x = (t >= off) ? ts[t - off] : 0;
        __syncthreads();
        ts[t] += x;
        __syncthreads();
    }
    g_boff[t] = ts[t] - v;   // exclusive
}

// phase 3: add block offsets; write total at rowptr[N]
__global__ void scan3_kernel(int N, int nb) {
    int i = blockIdx.x * blockDim.x + threadIdx.x;
    if (i < N) g_rowptr[i] += g_boff[i / SCAN_CHUNK];
    if (i == N) g_rowptr[N] = g_boff[nb - 1] + g_bsum[nb - 1];
}

// ---------------- CSR build: fill edge lists ----------------
__global__ void fill_kernel(const int* __restrict__ src,
                            const int* __restrict__ dst, int E) {
    int e = blockIdx.x * blockDim.x + threadIdx.x;
    if (e < E) {
        int d = dst[e];
        int pos = atomicAdd(&g_cur[d], 1);
        g_eidx[g_rowptr[d] + pos] = src[e];
    }
}

// ---------------- gather aggregation: agg[i] = BN?( x[i] + sum_{j->i} x[j] ) ----------------
template<int APPLY_BN>
__global__ void aggregate_kernel(const float* __restrict__ Xext, int N) {
    int i = (blockIdx.x * blockDim.x + threadIdx.x) >> 5;
    if (i >= N) return;
    int lane = threadIdx.x & 31;
    const float* X = APPLY_BN ? g_h : Xext;
    int base = g_rowptr[i];
    int end  = g_rowptr[i + 1];

    float4 acc = *reinterpret_cast<const float4*>(X + (size_t)i * HDIM + lane * 4);
    int e = base;
    for (; e + 4 <= end; e += 4) {
        int s0 = g_eidx[e], s1 = g_eidx[e + 1], s2 = g_eidx[e + 2], s3 = g_eidx[e + 3];
        float4 v0 = *reinterpret_cast<const float4*>(X + (size_t)s0 * HDIM + lane * 4);
        float4 v1 = *reinterpret_cast<const float4*>(X + (size_t)s1 * HDIM + lane * 4);
        float4 v2 = *reinterpret_cast<const float4*>(X + (size_t)s2 * HDIM + lane * 4);
        float4 v3 = *reinterpret_cast<const float4*>(X + (size_t)s3 * HDIM + lane * 4);
        acc.x += v0.x + v1.x + v2.x + v3.x;
        acc.y += v0.y + v1.y + v2.y + v3.y;
        acc.z += v0.z + v1.z + v2.z + v3.z;
        acc.w += v0.w + v1.w + v2.w + v3.w;
    }
    for (; e < end; e++) {
        int s = g_eidx[e];
        float4 v = *reinterpret_cast<const float4*>(X + (size_t)s * HDIM + lane * 4);
        acc.x += v.x; acc.y += v.y; acc.z += v.z; acc.w += v.w;
    }
    if (APPLY_BN) {
        float cnt = (float)(end - base + 1);
        float4 a = *reinterpret_cast<const float4*>(&g_coef[lane * 4]);
        float4 c = *reinterpret_cast<const float4*>(&g_coef[HDIM + lane * 4]);
        acc.x = fmaf(a.x, acc.x, cnt * c.x);
        acc.y = fmaf(a.y, acc.y, cnt * c.y);
        acc.z = fmaf(a.z, acc.z, cnt * c.z);
        acc.w = fmaf(a.w, acc.w, cnt * c.w);
    }
    *reinterpret_cast<float4*>(g_agg + (size_t)i * HDIM + lane * 4) = acc;
}

// ---------------- fused GEMM (R3 tiling): [N,128] @ [128,128] + bias, leaky ----------------
template<int MODE, int POOL>
__global__ void __launch_bounds__(256)
gemm_kernel(const float* __restrict__ W,
            const float* __restrict__ bias,
            const int* __restrict__ batch,
            int N) {
    __shared__ __align__(16) float As[16][72];
    __shared__ __align__(16) float Ws[16 * HDIM];
    __shared__ float csum[HDIM];
    __shared__ float csq [HDIM];

    const int tid  = threadIdx.x;
    const int tcol = tid & 31;
    const int trow = tid >> 5;
    const int row0 = blockIdx.x * 64;

    const float* X = (MODE == 0) ? g_agg : g_t;

    float acc[8][4];
#pragma unroll
    for (int i = 0; i < 8; i++)
#pragma unroll
        for (int j = 0; j < 4; j++) acc[i][j] = 0.f;

    const int lr = tid >> 2;
    const int lk = (tid & 3) * 4;

    for (int k0 = 0; k0 < HDIM; k0 += 16) {
        float4 av = make_float4(0.f, 0.f, 0.f, 0.f);
        int grow = row0 + lr;
        if (grow < N)
            av = *reinterpret_cast<const float4*>(X + (size_t)grow * HDIM + k0 + lk);
        As[lk + 0][lr] = av.x;
        As[lk + 1][lr] = av.y;
        As[lk + 2][lr] = av.z;
        As[lk + 3][lr] = av.w;

        const float4* wsrc = reinterpret_cast<const float4*>(W + k0 * HDIM);
        float4* wdst = reinterpret_cast<float4*>(Ws);
        wdst[tid]       = wsrc[tid];
        wdst[tid + 256] = wsrc[tid + 256];
        __syncthreads();

#pragma unroll
        for (int kk = 0; kk < 16; kk++) {
            float4 w  = *reinterpret_cast<float4*>(&Ws[kk * HDIM + tcol * 4]);
            float4 a0 = *reinterpret_cast<float4*>(&As[kk][trow * 8]);
            float4 a1 = *reinterpret_cast<float4*>(&As[kk][trow * 8 + 4]);
            float a[8] = {a0.x, a0.y, a0.z, a0.w, a1.x, a1.y, a1.z, a1.w};
#pragma unroll
            for (int i = 0; i < 8; i++) {
                acc[i][0] = fmaf(a[i], w.x, acc[i][0]);
                acc[i][1] = fmaf(a[i], w.y, acc[i][1]);
                acc[i][2] = fmaf(a[i], w.z, acc[i][2]);
                acc[i][3] = fmaf(a[i], w.w, acc[i][3]);
            }
        }
        __syncthreads();
    }

    float4 bv = *reinterpret_cast<const float4*>(bias + tcol * 4);

    if (MODE == 0) {
#pragma unroll
        for (int i = 0; i < 8; i++) {
            int grow = row0 + trow * 8 + i;
            if (grow < N) {
                float4 o;
                o.x = lrelu(acc[i][0] + bv.x);
                o.y = lrelu(acc[i][1] + bv.y);
                o.z = lrelu(acc[i][2] + bv.z);
                o.w = lrelu(acc[i][3] + bv.w);
                *reinterpret_cast<float4*>(g_t + (size_t)grow * HDIM + tcol * 4) = o;
            }
        }
    } else {
        float s0[4] = {0.f, 0.f, 0.f, 0.f};
        float s1[4] = {0.f, 0.f, 0.f, 0.f};
        int curg = -1;
        float p[4] = {0.f, 0.f, 0.f, 0.f};

#pragma unroll
        for (int i = 0; i < 8; i++) {
            int grow = row0 + trow * 8 + i;
            if (grow < N) {
                float4 o;
                o.x = lrelu(acc[i][0] + bv.x);
                o.y = lrelu(acc[i][1] + bv.y);
                o.z = lrelu(acc[i][2] + bv.z);
                o.w = lrelu(acc[i][3] + bv.w);
                s0[0] += o.x; s1[0] += o.x * o.x;
                s0[1] += o.y; s1[1] += o.y * o.y;
                s0[2] += o.z; s1[2] += o.z * o.z;
                s0[3] += o.w; s1[3] += o.w * o.w;
                if (!POOL) {
                    *reinterpret_cast<float4*>(g_h + (size_t)grow * HDIM + tcol * 4) = o;
                } else {
                    int g = batch[grow];
                    if (g != curg) {
                        if (curg >= 0) {
                            float* dstp = g_hg + (size_t)curg * HDIM + tcol * 4;
                            asm volatile("red.global.add.v4.f32 [%0], {%1, %2, %3, %4};"
                                         :: "l"(dstp), "f"(p[0]), "f"(p[1]), "f"(p[2]), "f"(p[3]) : "memory");
                        }
                        curg = g;
                        p[0] = p[1] = p[2] = p[3] = 0.f;
                    }
                    p[0] += o.x; p[1] += o.y; p[2] += o.z; p[3] += o.w;
                }
            }
        }
        if (POOL && curg >= 0) {
            float* dstp = g_hg + (size_t)curg * HDIM + tcol * 4;
            asm volatile("red.global.add.v4.f32 [%0], {%1, %2, %3, %4};"
                         :: "l"(dstp), "f"(p[0]), "f"(p[1]), "f"(p[2]), "f"(p[3]) : "memory");
        }

        if (tid < HDIM) { csum[tid] = 0.f; csq[tid] = 0.f; }
        __syncthreads();
#pragma unroll
        for (int j = 0; j < 4; j++) {
            atomicAdd(&csum[tcol * 4 + j], s0[j]);
            atomicAdd(&csq [tcol * 4 + j], s1[j]);
        }
        __syncthreads();
        if (tid < HDIM) {
            atomicAdd(&g_stats[tid],        (double)csum[tid]);
            atomicAdd(&g_stats[HDIM + tid], (double)csq[tid]);
        }
    }
}

// ---------------- BN coefficients ----------------
__global__ void coef_kernel(const float* __restrict__ gamma,
                            const float* __restrict__ beta, int N) {
    int c = threadIdx.x;
    double mean = g_stats[c] / (double)N;
    double var  = g_stats[HDIM + c] / (double)N - mean * mean;
    float a = (float)((double)gamma[c] / sqrt(var + (double)BN_EPS));
    g_coef[c]        = a;
    g_coef[HDIM + c] = beta[c] - a * (float)mean;
}

// ---------------- head ----------------
__global__ void head_kernel(const float* __restrict__ fcW1, const float* __restrict__ fcb1,
                            const float* __restrict__ fcW2, const float* __restrict__ fcb2,
                            float* __restrict__ out) {
    __shared__ float s[HDIM];
    __shared__ float y[HDIM];
    __shared__ float z[NCLS];
    __shared__ float red2[2];
    int g = blockIdx.x;
    int j = threadIdx.x;

    float cnt = g_cnt[g];
    s[j] = g_coef[j] * g_hg[g * HDIM + j] + g_coef[HDIM + j] * cnt;
    __syncthreads();

    float acc = fcb1[j];
#pragma unroll 8
    for (int k = 0; k < HDIM; k++) acc += s[k] * fcW1[k * HDIM + j];
    y[j] = lrelu(acc);
    __syncthreads();

    if (j < NCLS) {
        float acc2 = fcb2[j];
#pragma unroll 8
        for (int k = 0; k < HDIM; k++) acc2 += y[k] * fcW2[k * NCLS + j];
        z[j] = acc2;
    }
    __syncthreads();

    if (j == 0) {
        float m = z[0];
#pragma unroll
        for (int c = 1; c < NCLS; c++) m = fmaxf(m, z[c]);
        float se = 0.f;
#pragma unroll
        for (int c = 0; c < NCLS; c++) se += expf(z[c] - m);
        red2[0] = m;
        red2[1] = logf(se);
    }
    __syncthreads();
    if (j < NCLS) out[g * NCLS + j] = z[j] - red2[0] - red2[1];
}

// ---------------- launch ----------------
extern "C" void kernel_launch(void* const* d_in, const int* in_sizes, int n_in,
                              void* d_out, int out_size) {
    const float* x    = (const float*)d_in[0];
    const float* W1a  = (const float*)d_in[1];
    const float* b1a  = (const float*)d_in[2];
    const float* W1b  = (const float*)d_in[3];
    const float* b1b  = (const float*)d_in[4];
    const float* g1   = (const float*)d_in[5];
    const float* be1  = (const float*)d_in[6];
    const float* W2a  = (const float*)d_in[7];
    const float* b2a  = (const float*)d_in[8];
    const float* W2b  = (const float*)d_in[9];
    const float* b2b  = (const float*)d_in[10];
    const float* g2   = (const float*)d_in[11];
    const float* be2  = (const float*)d_in[12];
    const float* fcW1 = (const float*)d_in[13];
    const float* fcb1 = (const float*)d_in[14];
    const float* fcW2 = (const float*)d_in[15];
    const float* fcb2 = (const float*)d_in[16];
    const int* ei     = (const int*)d_in[17];   // int32 (JAX x64 disabled)
    const int* batch  = (const int*)d_in[18];   // int32
    float* out = (float*)d_out;

    const int N = in_sizes[0] / HDIM;
    const int E = in_sizes[17] / 2;
    const int* esrc = ei;
    const int* edst = ei + E;

    const int gemmBlocks = (N + 63) / 64;
    const int aggBlocks  = (N + 7) / 8;
    const int eBlocks    = (E + 255) / 256;
    const int scanBlocks = (N + SCAN_CHUNK - 1) / SCAN_CHUNK;

    // ---- CSR build (once, reused by both layers) ----
    zero_kernel<<<512, 256>>>(N);
    count_kernel<<<(N + 255) / 256, 256>>>(batch, N);
    hist_kernel<<<eBlocks, 256>>>(edst, E);
    scan1_kernel<<<scanBlocks, 256>>>(N);
    scan2_kernel<<<1, MAXBLK>>>(scanBlocks);
    scan3_kernel<<<(N + 256) / 256, 256>>>(N, scanBlocks);
    fill_kernel<<<eBlocks, 256>>>(esrc, edst, E);

    // ---- layer 1 ----
    aggregate_kernel<0><<<aggBlocks, 256>>>(x, N);
    gemm_kernel<0, 0><<<gemmBlocks, 256>>>(W1a, b1a, nullptr, N);
    gemm_kernel<1, 0><<<gemmBlocks, 256>>>(W1b, b1b, nullptr, N);
    coef_kernel<<<1, HDIM>>>(g1, be1, N);

    // ---- layer 2 (BN1 folded into aggregation) ----
    zstats_kernel<<<1, 256>>>();
    aggregate_kernel<1><<<aggBlocks, 256>>>(nullptr, N);
    gemm_kernel<0, 0><<<gemmBlocks, 256>>>(W2a, b2a, nullptr, N);
    gemm_kernel<1, 1><<<gemmBlocks, 256>>>(W2b, b2b, batch, N);
    coef_kernel<<<1, HDIM>>>(g2, be2, N);

    // ---- head ----
    head_kernel<<<GMAX, HDIM>>>(fcW1, fcb1, fcW2, fcb2, out);
}